// round 5
// baseline (speedup 1.0000x reference)
#include <cuda_runtime.h>

#define TT 2048
#define BB 4096
#define HH 10

// Phase-A -> Phase-B scratch: a_b[j] = c2[j] + Wih2[j,:] . y1last[b]
__device__ float g_a[BB * HH];

// tanh(a) = 1 - 2/(exp(2a)+1) via ex2/rcp approx; abs error ~1e-7
__device__ __forceinline__ float fast_tanh(float a) {
    float e;
    asm("ex2.approx.f32 %0, %1;" : "=f"(e) : "f"(a * 2.8853900817779268f));
    float r;
    asm("rcp.approx.f32 %0, %1;" : "=f"(r) : "f"(e + 1.0f));
    return fmaf(-2.0f, r, 1.0f);
}

// ---------------- Phase A: layer-1 time recurrence, keep last h, project with Wih2
// 320 threads = 10 warps; per warp: 3 groups of 10 lanes, 2 chains (sequences) per group
// => 6 sequences per warp, 60 per CTA, grid = 69.
__global__ __launch_bounds__(320, 1) void rnnA_kernel(
    const float* __restrict__ x,
    const float* __restrict__ Wih1, const float* __restrict__ Whh1,
    const float* __restrict__ bih1, const float* __restrict__ bhh1,
    const float* __restrict__ Wih2, const float* __restrict__ bih2,
    const float* __restrict__ bhh2)
{
    // [parity][warp][chain][group(3 real + 1 dummy)][10 values padded to 12]
    __shared__ float xch[2][10][2][4][12];

    const int warp = threadIdx.x >> 5;
    const int lane = threadIdx.x & 31;
    const int g = lane / 10;          // 3 = dummy group (lanes 30,31)
    const int j = lane - g * 10;

    const int gg = (g < 3) ? g : 0;
    const int base = (blockIdx.x * 10 + warp) * 6 + gg * 2;   // chain0 seq
    const int s0q = min(base, BB - 1);
    const int s1q = min(base + 1, BB - 1);

    float whh1[HH];
    const float wi0 = Wih1[j * 2 + 0];
    const float wi1 = Wih1[j * 2 + 1];
#pragma unroll
    for (int k = 0; k < HH; k++) whh1[k] = Whh1[j * HH + k];
    const float c1 = bih1[j] + bhh1[j];

    float h0[HH], h1[HH];
#pragma unroll
    for (int k = 0; k < HH; k++) { h0[k] = 0.f; h1[k] = 0.f; }

    const float4* xq0 = reinterpret_cast<const float4*>(x) + (size_t)s0q * (TT / 2);
    const float4* xq1 = reinterpret_cast<const float4*>(x) + (size_t)s1q * (TT / 2);

    float4 cur0[4], cur1[4];
#pragma unroll
    for (int i = 0; i < 4; i++) { cur0[i] = xq0[i]; cur1[i] = xq1[i]; }

    for (int tl = 0; tl < TT / 8; tl++) {
        // prefetch next tile (clamped; redundant-last-load unused)
        const int nb = min(tl + 1, TT / 8 - 1) * 4;
        float4 nxt0[4], nxt1[4];
#pragma unroll
        for (int i = 0; i < 4; i++) { nxt0[i] = xq0[nb + i]; nxt1[i] = xq1[nb + i]; }

#pragma unroll
        for (int s = 0; s < 8; s++) {
            const int p = s & 1;
            const float4 q0 = cur0[s >> 1];
            const float4 q1 = cur1[s >> 1];
            const float xa0 = (s & 1) ? q0.z : q0.x;
            const float xb0 = (s & 1) ? q0.w : q0.y;
            const float xa1 = (s & 1) ? q1.z : q1.x;
            const float xb1 = (s & 1) ? q1.w : q1.y;

            // chain 0
            float a0 = fmaf(wi0, xa0, c1);
            float b0 = wi1 * xb0;
            // chain 1
            float a1 = fmaf(wi0, xa1, c1);
            float b1 = wi1 * xb1;
#pragma unroll
            for (int k = 0; k < HH; k += 2) {
                a0 = fmaf(whh1[k],     h0[k],     a0);
                b0 = fmaf(whh1[k + 1], h0[k + 1], b0);
                a1 = fmaf(whh1[k],     h1[k],     a1);
                b1 = fmaf(whh1[k + 1], h1[k + 1], b1);
            }
            const float v0 = fast_tanh(a0 + b0);
            const float v1 = fast_tanh(a1 + b1);

            if (g < 3) {
                xch[p][warp][0][g][j] = v0;
                xch[p][warp][1][g][j] = v1;
            }
            __syncwarp();
            {
                const float4* r0 = reinterpret_cast<const float4*>(&xch[p][warp][0][g][0]);
                const float4 A = r0[0], B = r0[1];
                const float2 C = reinterpret_cast<const float2*>(&xch[p][warp][0][g][0])[4];
                h0[0] = A.x; h0[1] = A.y; h0[2] = A.z; h0[3] = A.w;
                h0[4] = B.x; h0[5] = B.y; h0[6] = B.z; h0[7] = B.w;
                h0[8] = C.x; h0[9] = C.y;
            }
            {
                const float4* r1 = reinterpret_cast<const float4*>(&xch[p][warp][1][g][0]);
                const float4 A = r1[0], B = r1[1];
                const float2 C = reinterpret_cast<const float2*>(&xch[p][warp][1][g][0])[4];
                h1[0] = A.x; h1[1] = A.y; h1[2] = A.z; h1[3] = A.w;
                h1[4] = B.x; h1[5] = B.y; h1[6] = B.z; h1[7] = B.w;
                h1[8] = C.x; h1[9] = C.y;
            }
        }
#pragma unroll
        for (int i = 0; i < 4; i++) { cur0[i] = nxt0[i]; cur1[i] = nxt1[i]; }
    }

    // Epilogue: a_b[j] = (bih2[j]+bhh2[j]) + Wih2[j,:] . y1last
    float w2[HH];
#pragma unroll
    for (int k = 0; k < HH; k++) w2[k] = Wih2[j * HH + k];
    const float c2 = bih2[j] + bhh2[j];

    float a0 = c2, a1 = c2;
#pragma unroll
    for (int k = 0; k < HH; k++) {
        a0 = fmaf(w2[k], h0[k], a0);
        a1 = fmaf(w2[k], h1[k], a1);
    }
    if (g < 3) {
        if (base < BB)     g_a[(size_t)base * HH + j]       = a0;
        if (base + 1 < BB) g_a[(size_t)(base + 1) * HH + j] = a1;
    }
}

// ---------------- Phase B: serial recurrence over b (the reference's missing-swapaxes
// scan), fused with the final FC. Single warp; lane j owns Whh2 row j.
__global__ void rnnB_kernel(const float* __restrict__ Whh2,
                            const float* __restrict__ Wfc,
                            const float* __restrict__ bfc,
                            float* __restrict__ out)
{
    const int lane = threadIdx.x;
    const int j = lane % 10;

    float V[HH];
#pragma unroll
    for (int k = 0; k < HH; k++) V[k] = Whh2[j * HH + k];

    float fcw[HH];
    float fcb = 0.f;
    if (lane < 4) {
#pragma unroll
        for (int k = 0; k < HH; k++) fcw[k] = Wfc[lane * HH + k];
        fcb = bfc[lane];
    } else {
#pragma unroll
        for (int k = 0; k < HH; k++) fcw[k] = 0.f;
    }

    // depth-8 register prefetch ring for a_b (L2-resident scratch)
    float pre[8];
#pragma unroll
    for (int i = 0; i < 8; i++) pre[i] = g_a[i * HH + j];

    float v = 0.f;   // this lane's component of g_{b-1}
    for (int tb = 0; tb < BB / 8; tb++) {
#pragma unroll
        for (int s = 0; s < 8; s++) {
            const int b = tb * 8 + s;
            const float av = pre[s];
            pre[s] = g_a[(size_t)min(b + 8, BB - 1) * HH + j];

            float h[HH];
#pragma unroll
            for (int k = 0; k < HH; k++) h[k] = __shfl_sync(0xFFFFFFFFu, v, k);

            // FC for step b-1 (off the serial critical path)
            if (b > 0 && lane < 4) {
                float o = fcb;
#pragma unroll
                for (int k = 0; k < HH; k++) o = fmaf(fcw[k], h[k], o);
                out[(b - 1) * 4 + lane] = o;
            }

            float acc0 = av, acc1 = 0.f;
#pragma unroll
            for (int k = 0; k < HH; k += 2) {
                acc0 = fmaf(V[k],     h[k],     acc0);
                acc1 = fmaf(V[k + 1], h[k + 1], acc1);
            }
            v = fast_tanh(acc0 + acc1);
        }
    }

    // final output row b = BB-1
    float h[HH];
#pragma unroll
    for (int k = 0; k < HH; k++) h[k] = __shfl_sync(0xFFFFFFFFu, v, k);
    if (lane < 4) {
        float o = fcb;
#pragma unroll
        for (int k = 0; k < HH; k++) o = fmaf(fcw[k], h[k], o);
        out[(BB - 1) * 4 + lane] = o;
    }
}

extern "C" void kernel_launch(void* const* d_in, const int* in_sizes, int n_in,
                              void* d_out, int out_size) {
    const float* x    = (const float*)d_in[0];
    const float* Wih1 = (const float*)d_in[1];
    const float* Whh1 = (const float*)d_in[2];
    const float* bih1 = (const float*)d_in[3];
    const float* bhh1 = (const float*)d_in[4];
    const float* Wih2 = (const float*)d_in[5];
    const float* Whh2 = (const float*)d_in[6];
    const float* bih2 = (const float*)d_in[7];
    const float* bhh2 = (const float*)d_in[8];
    const float* Wfc  = (const float*)d_in[9];
    const float* bfc  = (const float*)d_in[10];

    // 60 sequences per CTA (10 warps x 3 groups x 2 chains)
    dim3 gridA((BB + 59) / 60);
    rnnA_kernel<<<gridA, 320>>>(x, Wih1, Whh1, bih1, bhh1, Wih2, bih2, bhh2);
    rnnB_kernel<<<1, 32>>>(Whh2, Wfc, bfc, (float*)d_out);
}